// round 4
// baseline (speedup 1.0000x reference)
#include <cuda_runtime.h>
#include <cuda_bf16.h>

// BPMLL loss, factorized:
//   inner[b]  = (sum_{t==0} exp(x)) * (sum_{t==1} exp(-x))
//   length[b] = n_pos * n_neg
//   out       = sum_b inner[b] / length[b]
//
// B = 128, L = 1024, target int32.
//
// R4 design: 16 blocks x 1024 threads. Each block owns 8 rows (4 warps/row,
// 8 elements/thread). Rows are combined inside the block in a fixed order,
// then ONE fixed-point u64 atomic per block carries both the partial sum
// (low 56 bits, 2^32 fixed point -> order-independent integer add) and an
// arrival count (high 8 bits). This cuts same-address L2 atomic contention
// from 128 ops (~3.5K cyc serialized tail) to 16 (~450 cyc).

__device__ unsigned long long g_acc = 0ULL;

#define CNT_ONE   (1ULL << 56)
#define VAL_MASK  (CNT_ONE - 1ULL)
#define FP_SCALE  4294967296.0   // 2^32

#define ROWS_PER_BLOCK 8
#define WARPS_PER_ROW  4
#define BLOCK_THREADS  1024

__global__ void __launch_bounds__(BLOCK_THREADS, 1)
bpmll_fused_kernel(const float* __restrict__ inp,
                   const int* __restrict__ tgt,
                   float* __restrict__ out,
                   int L, int nBlocks) {
    const int tid = threadIdx.x;
    const int wid = tid >> 5;          // 0..31
    const int li  = tid & 31;
    const int r   = wid >> 2;          // row within block, 0..7
    const int q   = wid & 3;           // quarter of the row, 0..3

    const int b = blockIdx.x * ROWS_PER_BLOCK + r;   // global row
    const float4* __restrict__ x4 = (const float4*)(inp + (size_t)b * L);
    const int4*   __restrict__ t4 = (const int4*)(tgt + (size_t)b * L);

    // row has L/4 = 256 float4; this warp's quarter covers [q*64, q*64+64)
    const int i0 = q * 64 + li;
    const int i1 = i0 + 32;

    float4 v0 = x4[i0];
    int4   t0 = t4[i0];
    float4 v1 = x4[i1];
    int4   t1 = t4[i1];

    float s_neg = 0.0f, s_pinv = 0.0f;
    int   np    = 0;

    #define ACCUM(vv, tt)                                                   \
        {                                                                   \
            bool p = ((tt) == 1);                                           \
            float e = __expf(p ? -(vv) : (vv));                             \
            s_pinv += p ? e : 0.0f;                                         \
            s_neg  += p ? 0.0f : e;                                         \
            np += __popc(__ballot_sync(0xffffffffu, p));                    \
        }

    ACCUM(v0.x, t0.x) ACCUM(v0.y, t0.y) ACCUM(v0.z, t0.z) ACCUM(v0.w, t0.w)
    ACCUM(v1.x, t1.x) ACCUM(v1.y, t1.y) ACCUM(v1.z, t1.z) ACCUM(v1.w, t1.w)
    #undef ACCUM

    // warp reduce the two float sums (np is already warp-uniform via ballot)
    #pragma unroll
    for (int off = 16; off > 0; off >>= 1) {
        s_neg  += __shfl_xor_sync(0xffffffffu, s_neg,  off);
        s_pinv += __shfl_xor_sync(0xffffffffu, s_pinv, off);
    }

    __shared__ float sh_neg[ROWS_PER_BLOCK][WARPS_PER_ROW];
    __shared__ float sh_pinv[ROWS_PER_BLOCK][WARPS_PER_ROW];
    __shared__ int   sh_np[ROWS_PER_BLOCK][WARPS_PER_ROW];
    __shared__ float sh_loss[ROWS_PER_BLOCK];

    if (li == 0) {
        sh_neg[r][q]  = s_neg;
        sh_pinv[r][q] = s_pinv;
        sh_np[r][q]   = np;
    }
    __syncthreads();

    if (tid < ROWS_PER_BLOCK) {
        float tn = 0.0f, tp = 0.0f;
        int   n  = 0;
        #pragma unroll
        for (int w = 0; w < WARPS_PER_ROW; ++w) {
            tn += sh_neg[tid][w];
            tp += sh_pinv[tid][w];
            n  += sh_np[tid][w];
        }
        float fnp = (float)n;
        float fnn = (float)L - fnp;
        sh_loss[tid] = (tn * tp) / (fnp * fnn);
    }
    __syncthreads();

    if (tid == 0) {
        double acc = 0.0;
        #pragma unroll
        for (int i = 0; i < ROWS_PER_BLOCK; ++i) acc += (double)sh_loss[i];

        unsigned long long myval =
            (unsigned long long)llrint(acc * FP_SCALE) + CNT_ONE;
        unsigned long long old = atomicAdd(&g_acc, myval);

        if ((old >> 56) == (unsigned long long)(nBlocks - 1)) {
            unsigned long long total = (old + myval) & VAL_MASK;
            out[0] = (float)((double)total * (1.0 / FP_SCALE));
            g_acc = 0ULL;   // reset for next graph replay
        }
    }
}

extern "C" void kernel_launch(void* const* d_in, const int* in_sizes, int n_in,
                              void* d_out, int out_size) {
    const float* inp = (const float*)d_in[0];
    const int*   tgt = (const int*)d_in[1];
    float* out = (float*)d_out;

    const int B = 128;
    const int L = in_sizes[0] / B;          // 1024
    const int nBlocks = B / ROWS_PER_BLOCK; // 16

    bpmll_fused_kernel<<<nBlocks, BLOCK_THREADS>>>(inp, tgt, out, L, nBlocks);
}

// round 6
// speedup vs baseline: 1.0093x; 1.0093x over previous
#include <cuda_runtime.h>
#include <cuda_bf16.h>

// BPMLL loss, factorized:
//   inner[b]  = (sum_{t==0} exp(x)) * (sum_{t==1} exp(-x))
//   length[b] = n_pos * n_neg
//   out       = sum_b inner[b] / length[b]
//
// B = 128, L = 1024, target int32.
//
// R6: 128 blocks x 256 threads. One float4 + int4 load per thread,
// branchless __expf, n_pos via ballot/popc (kills one shfl-reduce chain;
// NOTE: redux.sync.add.f32 does NOT exist on sm_103a -> plain shfl chains).
// Finish: single u64 fixed-point atomic (low 56 bits = 2^32 fixed-point sum,
// high 8 bits = arrival counter) -> deterministic, no fence, no 2nd phase.

__device__ unsigned long long g_acc = 0ULL;

#define CNT_ONE   (1ULL << 56)
#define VAL_MASK  (CNT_ONE - 1ULL)
#define FP_SCALE  4294967296.0   // 2^32

template<int BLOCK>
__global__ void __launch_bounds__(BLOCK, 1)
bpmll_fused_kernel(const float* __restrict__ inp,
                   const int* __restrict__ tgt,
                   float* __restrict__ out,
                   int L, int B) {
    const int b = blockIdx.x;
    const float4* __restrict__ x4 = (const float4*)(inp + (size_t)b * L);
    const int4*   __restrict__ t4 = (const int4*)(tgt + (size_t)b * L);
    const int nvec = L >> 2;   // 256 for L=1024 -> exactly one element per thread

    float s_neg  = 0.0f;   // sum exp(x) over negatives
    float s_pinv = 0.0f;   // sum exp(-x) over positives
    int   np     = 0;      // warp-uniform positive count (via ballot)

    for (int i = threadIdx.x; i < nvec; i += BLOCK) {
        float4 v = x4[i];
        int4   t = t4[i];
        {
            bool p = (t.x == 1); float e = __expf(p ? -v.x : v.x);
            s_pinv += p ? e : 0.0f; s_neg += p ? 0.0f : e;
            np += __popc(__ballot_sync(0xffffffffu, p));
        }
        {
            bool p = (t.y == 1); float e = __expf(p ? -v.y : v.y);
            s_pinv += p ? e : 0.0f; s_neg += p ? 0.0f : e;
            np += __popc(__ballot_sync(0xffffffffu, p));
        }
        {
            bool p = (t.z == 1); float e = __expf(p ? -v.z : v.z);
            s_pinv += p ? e : 0.0f; s_neg += p ? 0.0f : e;
            np += __popc(__ballot_sync(0xffffffffu, p));
        }
        {
            bool p = (t.w == 1); float e = __expf(p ? -v.w : v.w);
            s_pinv += p ? e : 0.0f; s_neg += p ? 0.0f : e;
            np += __popc(__ballot_sync(0xffffffffu, p));
        }
    }

    // warp reduce (two chains; np already warp-uniform via ballot)
    #pragma unroll
    for (int off = 16; off > 0; off >>= 1) {
        s_neg  += __shfl_xor_sync(0xffffffffu, s_neg,  off);
        s_pinv += __shfl_xor_sync(0xffffffffu, s_pinv, off);
    }

    constexpr int NWARP = BLOCK / 32;
    __shared__ float sh_neg[NWARP], sh_pinv[NWARP];
    __shared__ int   sh_np[NWARP];
    const int wid = threadIdx.x >> 5;
    const int lid = threadIdx.x & 31;
    if (lid == 0) { sh_neg[wid] = s_neg; sh_pinv[wid] = s_pinv; sh_np[wid] = np; }
    __syncthreads();

    if (threadIdx.x == 0) {
        float tn = 0.0f, tp = 0.0f;
        int   n  = 0;
        #pragma unroll
        for (int w = 0; w < NWARP; ++w) { tn += sh_neg[w]; tp += sh_pinv[w]; n += sh_np[w]; }
        float fnp = (float)n;
        float fnn = (float)L - fnp;
        float loss = (tn * tp) / (fnp * fnn);

        unsigned long long myval =
            (unsigned long long)llrint((double)loss * FP_SCALE) + CNT_ONE;
        unsigned long long old = atomicAdd(&g_acc, myval);

        if ((old >> 56) == (unsigned long long)(B - 1)) {
            unsigned long long total = (old + myval) & VAL_MASK;
            out[0] = (float)((double)total * (1.0 / FP_SCALE));
            g_acc = 0ULL;   // reset for next graph replay
        }
    }
}

extern "C" void kernel_launch(void* const* d_in, const int* in_sizes, int n_in,
                              void* d_out, int out_size) {
    const float* inp = (const float*)d_in[0];
    const int*   tgt = (const int*)d_in[1];
    float* out = (float*)d_out;

    const int B = 128;
    const int L = in_sizes[0] / B;   // 1024

    constexpr int BLOCK = 256;
    bpmll_fused_kernel<BLOCK><<<B, BLOCK>>>(inp, tgt, out, L, B);
}